// round 5
// baseline (speedup 1.0000x reference)
#include <cuda_runtime.h>
#include <cuda_bf16.h>
#include <cstdint>

// ---------------- static scratch (no allocations allowed) ----------------
#define MAX_NODES 10000
#define MAX_G     128
#define D_HID_C   512
#define D_FEAT_C  128

__device__ float g_hid[MAX_NODES * D_HID_C];            // relu(X@W1+b1)
__device__ float g_h[MAX_NODES * D_FEAT_C];             // final h (fp32, for node_out)
__device__ __nv_bfloat16 g_h16[MAX_NODES * D_FEAT_C];   // bf16 copy for edge gather
__device__ float g_glob[MAX_G];
__device__ float g_wsum[MAX_G];
__device__ int   g_eprefix[MAX_G + 1];
__device__ int   g_nodeid[MAX_G];

// packed fp32 FMA: d = a*b + d  (elementwise on 2x fp32 packed in 64-bit)
#define FMA_F32X2(d, a, b) \
    asm("fma.rn.f32x2 %0, %1, %2, %0;" : "+l"(d) : "l"(a), "l"(b))

// ---------------- setup ----------------
__global__ void setup_kernel(const int* __restrict__ n_node,
                             const int* __restrict__ n_edge, int G) {
    int t = threadIdx.x;
    for (int g = t; g < G; g += blockDim.x) { g_glob[g] = 0.f; g_wsum[g] = 0.f; }
    if (t == 0) {
        int pe = 0, pn = 0;
        g_eprefix[0] = 0;
        for (int g = 0; g < G; g++) {
            pe += n_edge[g];
            g_eprefix[g + 1] = pe;
            pn += n_node[g];
            g_nodeid[g] = pn - 1;
        }
    }
}

// ---------------- GEMM with packed f32x2 FMAs ----------------
// C = (relu?)(A[MxK] @ B[KxN] + bias); optional bf16 copy of C.
// A-tile stored DUPLICATED in smem: As2[k][2m]=As2[k][2m+1]=A[m][k], so one
// LDS.128 yields two (a_i,a_i) multiplier pairs. B pairs are natural.
// NT threads = (BM/TM)*(BN/TN). Requires N%BN==0, K%BK==0, TN==8, TM%2==0.
template <int BM, int BN, int BK, int TM, int TN, int RELU, int WB16, int NT>
__global__ __launch_bounds__(NT)
void gemm_f32x2_kernel(const float* __restrict__ A, const float* __restrict__ B,
                       const float* __restrict__ bias, float* __restrict__ C,
                       __nv_bfloat16* __restrict__ C16,
                       int M, int N, int K) {
    __shared__ float As2[BK][2 * BM + 8];
    __shared__ float Bs[BK][BN + 8];

    const int tid = threadIdx.x;
    const int bm = blockIdx.y * BM;
    const int bn = blockIdx.x * BN;
    const int NTX = BN / TN;                 // threads along n
    const int tx = tid % NTX;
    const int ty = tid / NTX;

    unsigned long long acc[TM][TN / 2];
    #pragma unroll
    for (int i = 0; i < TM; i++)
        #pragma unroll
        for (int j = 0; j < TN / 2; j++) acc[i][j] = 0ull;

    const int A_F4 = (BM * BK) / (4 * NT);   // float4 loads per thread (A tile)
    const int B_F4 = (BK * BN) / (4 * NT);

    for (int k0 = 0; k0 < K; k0 += BK) {
        // A tile [BM x BK] -> transposed + duplicated
        #pragma unroll
        for (int it = 0; it < A_F4; it++) {
            int idx = tid + it * NT;
            int row = idx / (BK / 4);
            int cs  = idx % (BK / 4);
            float4 v = make_float4(0.f, 0.f, 0.f, 0.f);
            int gr = bm + row;
            if (gr < M) v = *(const float4*)(A + (size_t)gr * K + k0 + cs * 4);
            As2[cs * 4 + 0][2 * row] = v.x; As2[cs * 4 + 0][2 * row + 1] = v.x;
            As2[cs * 4 + 1][2 * row] = v.y; As2[cs * 4 + 1][2 * row + 1] = v.y;
            As2[cs * 4 + 2][2 * row] = v.z; As2[cs * 4 + 2][2 * row + 1] = v.z;
            As2[cs * 4 + 3][2 * row] = v.w; As2[cs * 4 + 3][2 * row + 1] = v.w;
        }
        // B tile [BK x BN]
        #pragma unroll
        for (int it = 0; it < B_F4; it++) {
            int idx = tid + it * NT;
            int kr = idx / (BN / 4);
            int cs = idx % (BN / 4);
            float4 v = *(const float4*)(B + (size_t)(k0 + kr) * N + bn + cs * 4);
            *(float4*)&Bs[kr][cs * 4] = v;
        }
        __syncthreads();

        #pragma unroll
        for (int k = 0; k < BK; k++) {
            unsigned long long av[TM], bv[TN / 2];
            #pragma unroll
            for (int p = 0; p < TM / 2; p++) {
                ulonglong2 t = *(const ulonglong2*)&As2[k][(ty * TM + p * 2) * 2];
                av[p * 2] = t.x; av[p * 2 + 1] = t.y;
            }
            #pragma unroll
            for (int p = 0; p < TN / 4; p++) {
                ulonglong2 t = *(const ulonglong2*)&Bs[k][tx * TN + p * 4];
                bv[p * 2] = t.x; bv[p * 2 + 1] = t.y;
            }
            #pragma unroll
            for (int i = 0; i < TM; i++)
                #pragma unroll
                for (int j = 0; j < TN / 2; j++)
                    FMA_F32X2(acc[i][j], av[i], bv[j]);
        }
        __syncthreads();
    }

    // epilogue
    float bb[TN];
    #pragma unroll
    for (int p = 0; p < TN / 4; p++)
        *(float4*)&bb[p * 4] = *(const float4*)(bias + bn + tx * TN + p * 4);

    #pragma unroll
    for (int i = 0; i < TM; i++) {
        int gr = bm + ty * TM + i;
        if (gr >= M) continue;
        float vout[TN];
        #pragma unroll
        for (int j = 0; j < TN / 2; j++) {
            float lo = __uint_as_float((unsigned)(acc[i][j] & 0xFFFFFFFFull));
            float hi = __uint_as_float((unsigned)(acc[i][j] >> 32));
            lo += bb[2 * j]; hi += bb[2 * j + 1];
            if (RELU) { lo = fmaxf(lo, 0.f); hi = fmaxf(hi, 0.f); }
            vout[2 * j] = lo; vout[2 * j + 1] = hi;
        }
        float* crow = C + (size_t)gr * N + bn + tx * TN;
        #pragma unroll
        for (int p = 0; p < TN / 4; p++)
            *(float4*)(crow + p * 4) = *(float4*)&vout[p * 4];
        if (WB16) {
            __nv_bfloat162* c16 = (__nv_bfloat162*)(C16 + (size_t)gr * N + bn + tx * TN);
            #pragma unroll
            for (int j = 0; j < TN / 2; j++)
                c16[j] = __float22bfloat162_rn(make_float2(vout[2 * j], vout[2 * j + 1]));
        }
    }
}

// ---------------- edge kernel (bf16 h rows: 256B/row) ----------------
// One warp per 64 contiguous edges. Lane l owns uint2 #l (4 bf16 dims).
__global__ __launch_bounds__(256)
void edge_kernel(const float* __restrict__ edges,
                 const int* __restrict__ senders,
                 const int* __restrict__ receivers,
                 int E, int G) {
    const int CHUNK = 64;
    int wid  = (blockIdx.x * blockDim.x + threadIdx.x) >> 5;
    int lane = threadIdx.x & 31;
    int e0 = wid * CHUNK;
    if (e0 >= E) return;
    int e1 = min(e0 + CHUNK, E);

    int lo = 0, hi = G;
    while (lo + 1 < hi) {
        int mid = (lo + hi) >> 1;
        if (g_eprefix[mid] <= e0) lo = mid; else hi = mid;
    }
    int gid  = lo;
    int next = g_eprefix[gid + 1];

    const uint2* __restrict__ h2 = (const uint2*)g_h16;   // 32 uint2 per row
    float part = 0.f, wpart = 0.f;

    for (int e = e0; e < e1; e++) {
        if (e >= next) {
            float r = part;
            #pragma unroll
            for (int o = 16; o > 0; o >>= 1) r += __shfl_xor_sync(0xFFFFFFFFu, r, o);
            if (lane == 0) {
                atomicAdd(&g_glob[gid], r);
                atomicAdd(&g_wsum[gid], wpart);
            }
            part = 0.f; wpart = 0.f;
            do { gid++; } while (g_eprefix[gid + 1] <= e);
            next = g_eprefix[gid + 1];
        }
        int   s = __ldg(&senders[e]);
        int   r = __ldg(&receivers[e]);
        float w = __ldg(&edges[e]);
        uint2 ua = h2[(size_t)s * 32 + lane];
        uint2 ub = h2[(size_t)r * 32 + lane];
        float2 a0 = __bfloat1622float2(*(__nv_bfloat162*)&ua.x);
        float2 a1 = __bfloat1622float2(*(__nv_bfloat162*)&ua.y);
        float2 b0 = __bfloat1622float2(*(__nv_bfloat162*)&ub.x);
        float2 b1 = __bfloat1622float2(*(__nv_bfloat162*)&ub.y);
        float d0 = a0.x - b0.x, d1 = a0.y - b0.y;
        float d2 = a1.x - b1.x, d3 = a1.y - b1.y;
        part = fmaf(w, fmaf(d0, d0, fmaf(d1, d1, fmaf(d2, d2, d3 * d3))), part);
        if (lane == 0) wpart += w;
    }
    float r2 = part;
    #pragma unroll
    for (int o = 16; o > 0; o >>= 1) r2 += __shfl_xor_sync(0xFFFFFFFFu, r2, o);
    if (lane == 0) {
        atomicAdd(&g_glob[gid], r2);
        atomicAdd(&g_wsum[gid], wpart);
    }
}

// ---------------- finalize ----------------
__global__ void finalize_kernel(float* __restrict__ out,
                                int G, int D, int loss_idx) {
    int b = blockIdx.x;
    if (b < G) {
        int row = g_nodeid[b];
        for (int j = threadIdx.x; j < D; j += blockDim.x)
            out[b * D + j] = g_h[(size_t)row * D + j];
    } else {
        __shared__ float s[128];
        float v = 0.f;
        for (int g = threadIdx.x; g < G; g += blockDim.x) {
            float w = g_wsum[g];
            v += (w != 0.f) ? (g_glob[g] / w) : 0.f;
        }
        s[threadIdx.x] = v;
        __syncthreads();
        for (int o = 64; o > 0; o >>= 1) {
            if (threadIdx.x < o) s[threadIdx.x] += s[threadIdx.x + o];
            __syncthreads();
        }
        if (threadIdx.x == 0) out[loss_idx] = s[0] / (float)G;
    }
}

// ---------------- launch ----------------
extern "C" void kernel_launch(void* const* d_in, const int* in_sizes, int n_in,
                              void* d_out, int out_size) {
    const float* nodes     = (const float*)d_in[0];
    const float* edges     = (const float*)d_in[1];
    const int*   senders   = (const int*)d_in[2];
    const int*   receivers = (const int*)d_in[3];
    const int*   n_node    = (const int*)d_in[4];
    const int*   n_edge    = (const int*)d_in[5];
    const float* W1        = (const float*)d_in[6];
    const float* b1        = (const float*)d_in[7];
    const float* W2        = (const float*)d_in[8];
    const float* b2        = (const float*)d_in[9];
    float* out = (float*)d_out;

    const int D_HID  = in_sizes[7];               // 512
    const int D_FEAT = in_sizes[9];               // 128
    const int N      = in_sizes[0] / D_FEAT;      // 10000
    const int E      = in_sizes[2];               // 640000
    const int G      = in_sizes[4];               // 100

    static float* hid = nullptr;
    static float* h   = nullptr;
    static __nv_bfloat16* h16 = nullptr;
    if (!hid) {
        cudaGetSymbolAddress((void**)&hid, g_hid);
        cudaGetSymbolAddress((void**)&h,   g_h);
        cudaGetSymbolAddress((void**)&h16, g_h16);
    }

    setup_kernel<<<1, 128>>>(n_node, n_edge, G);

    // GEMM1: hid = relu(nodes @ W1 + b1)  [N x 512], tile 128x128, 256 thr
    {
        dim3 grid(D_HID / 128, (N + 127) / 128);
        gemm_f32x2_kernel<128, 128, 16, 8, 8, 1, 0, 256>
            <<<grid, 256>>>(nodes, W1, b1, hid, nullptr, N, D_HID, D_FEAT);
    }
    // GEMM2: h = hid @ W2 + b2  [N x 128], tile 32x128, 128 thr (313 blocks)
    {
        dim3 grid(D_FEAT / 128, (N + 31) / 32);
        gemm_f32x2_kernel<32, 128, 16, 4, 8, 0, 1, 128>
            <<<grid, 128>>>(hid, W2, b2, h, h16, N, D_FEAT, D_HID);
    }
    // edge phase
    {
        int warps  = (E + 63) / 64;
        int blocks = (warps * 32 + 255) / 256;
        edge_kernel<<<blocks, 256>>>(edges, senders, receivers, E, G);
    }
    finalize_kernel<<<G + 1, 128>>>(out, G, D_FEAT, out_size - 1);
}